// round 10
// baseline (speedup 1.0000x reference)
#include <cuda_runtime.h>
#include <cuda_bf16.h>
#include <cstdint>

// Problem sizes (fixed by the reference)
#define LL 16384
#define HH 1024
#define PP 512
#define NC 256          // scan chunks
#define TT 64           // chunk length  (NC*TT == LL)

// ---------------- device scratch (static, allocation-free) ----------------
__device__ __nv_bfloat16 g_ubf [LL * HH];     // bf16(u)
__device__ __nv_bfloat16 g_Bre [PP * HH];     // bf16(Re B_bar)
__device__ __nv_bfloat16 g_Bim [PP * HH];     // bf16(Im B_bar)
__device__ __nv_bfloat16 g_Cre [HH * PP];     // bf16(C_re)
__device__ __nv_bfloat16 g_Cim [HH * PP];     // bf16(C_im)
__device__ float2        g_lam [PP];          // Lambda_bar
__device__ float2        g_scale[PP];         // (Lambda_bar-1)/Lambda
__device__ __nv_bfloat16 g_Bure[LL * PP];     // bf16(Bu_re)
__device__ __nv_bfloat16 g_Buim[LL * PP];     // bf16(Bu_im)
__device__ float2        g_e    [NC * PP];    // chunk-local end states
__device__ float2        g_carry[NC * PP];    // carry into each chunk
__device__ __nv_bfloat16 g_xre [LL * PP];     // bf16(Re x)
__device__ __nv_bfloat16 g_xim [LL * PP];     // bf16(Im x)

// ---------------- PTX helpers ----------------
__device__ __forceinline__ uint32_t s2u(const void* p) {
    return (uint32_t)__cvta_generic_to_shared(p);
}
__device__ __forceinline__ void cpa16(uint32_t dst, const void* src) {
    asm volatile("cp.async.cg.shared.global [%0], [%1], 16;\n" :: "r"(dst), "l"(src));
}
__device__ __forceinline__ void ldsm_x4(uint32_t* r, uint32_t addr) {
    asm volatile("ldmatrix.sync.aligned.m8n8.x4.shared.b16 {%0,%1,%2,%3}, [%4];\n"
                 : "=r"(r[0]), "=r"(r[1]), "=r"(r[2]), "=r"(r[3]) : "r"(addr));
}
__device__ __forceinline__ void mma_bf16(float* c, const uint32_t* a, uint32_t b0, uint32_t b1) {
    asm volatile(
        "mma.sync.aligned.m16n8k16.row.col.f32.bf16.bf16.f32 "
        "{%0,%1,%2,%3}, {%4,%5,%6,%7}, {%8,%9}, {%0,%1,%2,%3};\n"
        : "+f"(c[0]), "+f"(c[1]), "+f"(c[2]), "+f"(c[3])
        : "r"(a[0]), "r"(a[1]), "r"(a[2]), "r"(a[3]), "r"(b0), "r"(b1));
}
__device__ __forceinline__ uint32_t packbf2(float x, float y) {
    __nv_bfloat162 v = __floats2bfloat162_rn(x, y);
    return *reinterpret_cast<uint32_t*>(&v);
}
__device__ __forceinline__ float bf16r(float x) {
    return __bfloat162float(__float2bfloat16(x));
}

// ---------------- prep kernels ----------------
__global__ void prep_lambda_k(const float* __restrict__ Lre,
                              const float* __restrict__ Lim,
                              const float* __restrict__ lstep) {
    int p = blockIdx.x * blockDim.x + threadIdx.x;
    if (p >= PP) return;
    float dt = expf(lstep[p]);
    float lr = Lre[p], li = Lim[p];
    float ar = lr * dt, ai = li * dt;
    float m  = expf(ar);
    float lbr = m * cosf(ai);
    float lbi = m * sinf(ai);
    g_lam[p] = make_float2(lbr, lbi);
    float d  = lr * lr + li * li;
    float nr = lbr - 1.0f;
    float sr = (nr * lr + lbi * li) / d;
    float si = (lbi * lr - nr * li) / d;
    g_scale[p] = make_float2(sr, si);
}

__global__ void prep_bbar_k(const float* __restrict__ Bre,
                            const float* __restrict__ Bim) {
    int i = blockIdx.x * blockDim.x + threadIdx.x;
    if (i >= PP * HH) return;
    int p = i / HH;
    float2 s = g_scale[p];
    float br = Bre[i], bi = Bim[i];
    g_Bre[i] = __float2bfloat16(s.x * br - s.y * bi);
    g_Bim[i] = __float2bfloat16(s.x * bi + s.y * br);
}

__global__ void prep_cbf_k(const float* __restrict__ Cre,
                           const float* __restrict__ Cim) {
    int i = blockIdx.x * blockDim.x + threadIdx.x;
    if (i >= HH * PP) return;
    g_Cre[i] = __float2bfloat16(Cre[i]);
    g_Cim[i] = __float2bfloat16(Cim[i]);
}

__global__ void prep_ubf_k(const float* __restrict__ u) {
    int i = blockIdx.x * blockDim.x + threadIdx.x;
    int base = i * 4;
    if (base >= LL * HH) return;
    float4 v = *reinterpret_cast<const float4*>(&u[base]);
    g_ubf[base + 0] = __float2bfloat16(v.x);
    g_ubf[base + 1] = __float2bfloat16(v.y);
    g_ubf[base + 2] = __float2bfloat16(v.z);
    g_ubf[base + 3] = __float2bfloat16(v.w);
}

// =====================================================================
// GEMM 1 (mma.sync): Bu(L,P) = ubf(L,H) x {Bre,Bim}(P,H)^T, dual output.
// Block 128(M) x 128(N), K staged by 64, 3-stage cp.async ring, 8 warps.
// Warp tile: 64(M) x 32(N), both outputs. mma:ldsm = 4.0.
// Stage = A 16K + Br 16K + Bi 16K = 48KB; 3 stages = 144KB.
// =====================================================================
__global__ __launch_bounds__(256) void gemm_bu_mma() {
    extern __shared__ __align__(16) unsigned char sm_[];
    const int tid = threadIdx.x;
    const int lane = tid & 31, warp = tid >> 5;
    const int warpM = warp & 1;          // 2 warps over M
    const int warpN = warp >> 1;         // 4 warps over N
    const int row0 = blockIdx.y * 128;   // L
    const int col0 = blockIdx.x * 128;   // P
    const uint32_t sb = s2u(sm_);

    float cR[4][4][4] = {}, cI[4][4][4] = {};

    auto load_stage = [&](int st, int k0) {
        uint32_t base = sb + st * 49152;
#pragma unroll
        for (int i = 0; i < 4; i++) {             // A: 128 rows x 64 K
            int id = tid + i * 256;
            int r = id >> 3, c = id & 7;
            uint32_t o = (uint32_t)(r * 128 + ((c ^ (r & 7)) << 4));
            cpa16(base + o, &g_ubf[(size_t)(row0 + r) * HH + k0 + c * 8]);
        }
#pragma unroll
        for (int i = 0; i < 4; i++) {             // Br, Bi: 128 rows x 64 K each
            int id = tid + i * 256;
            int r = id >> 3, c = id & 7;
            uint32_t o = (uint32_t)(r * 128 + ((c ^ (r & 7)) << 4));
            cpa16(base + 16384 + o, &g_Bre[(size_t)(col0 + r) * HH + k0 + c * 8]);
            cpa16(base + 32768 + o, &g_Bim[(size_t)(col0 + r) * HH + k0 + c * 8]);
        }
        asm volatile("cp.async.commit_group;\n");
    };

    const int T = HH / 64;   // 16
    load_stage(0, 0);
    load_stage(1, 64);
    for (int t = 0; t < T; t++) {
        if (t + 1 < T) asm volatile("cp.async.wait_group 1;\n" ::: "memory");
        else           asm volatile("cp.async.wait_group 0;\n" ::: "memory");
        __syncthreads();
        if (t + 2 < T) load_stage((t + 2) % 3, (t + 2) * 64);

        uint32_t a0 = sb + (t % 3) * 49152;
#pragma unroll
        for (int kk = 0; kk < 4; kk++) {
            uint32_t af[4][4];
#pragma unroll
            for (int mt = 0; mt < 4; mt++) {
                int r = warpM * 64 + mt * 16 + (lane & 7) + ((lane >> 3) & 1) * 8;
                int c = kk * 2 + (lane >> 4);
                ldsm_x4(af[mt], a0 + r * 128 + ((c ^ (r & 7)) << 4));
            }
            uint32_t bR[2][4], bI[2][4];   // pair pj covers n8 tiles 2pj, 2pj+1
#pragma unroll
            for (int pj = 0; pj < 2; pj++) {
                int g = lane >> 3;
                int n = warpN * 32 + (pj * 2 + (g >> 1)) * 8 + (lane & 7);
                int c = kk * 2 + (g & 1);
                uint32_t off = n * 128 + ((c ^ (n & 7)) << 4);
                ldsm_x4(bR[pj], a0 + 16384 + off);
                ldsm_x4(bI[pj], a0 + 32768 + off);
            }
#pragma unroll
            for (int mt = 0; mt < 4; mt++)
#pragma unroll
                for (int nt = 0; nt < 4; nt++) {
                    mma_bf16(cR[mt][nt], af[mt],
                             bR[nt >> 1][(nt & 1) * 2], bR[nt >> 1][(nt & 1) * 2 + 1]);
                    mma_bf16(cI[mt][nt], af[mt],
                             bI[nt >> 1][(nt & 1) * 2], bI[nt >> 1][(nt & 1) * 2 + 1]);
                }
        }
        __syncthreads();
    }

#pragma unroll
    for (int mt = 0; mt < 4; mt++) {
        int l0 = row0 + warpM * 64 + mt * 16 + (lane >> 2);
#pragma unroll
        for (int nt = 0; nt < 4; nt++) {
            int p = col0 + warpN * 32 + nt * 8 + (lane & 3) * 2;
            *reinterpret_cast<uint32_t*>(&g_Bure[(size_t)l0 * PP + p])       = packbf2(cR[mt][nt][0], cR[mt][nt][1]);
            *reinterpret_cast<uint32_t*>(&g_Bure[(size_t)(l0 + 8) * PP + p]) = packbf2(cR[mt][nt][2], cR[mt][nt][3]);
            *reinterpret_cast<uint32_t*>(&g_Buim[(size_t)l0 * PP + p])       = packbf2(cI[mt][nt][0], cI[mt][nt][1]);
            *reinterpret_cast<uint32_t*>(&g_Buim[(size_t)(l0 + 8) * PP + p]) = packbf2(cI[mt][nt][2], cI[mt][nt][3]);
        }
    }
}

// ---------------- scan pass A: chunk-local end states ----------------
__global__ void scanA_kernel() {
    int p = blockIdx.x * blockDim.x + threadIdx.x;
    int c = blockIdx.y;
    float2 lam = g_lam[p];
    float er = 0.f, ei = 0.f;
    long base = (long)c * TT * PP + p;
    for (int j = 0; j < TT; j++) {
        float br = __bfloat162float(g_Bure[base + (long)j * PP]);
        float bi = __bfloat162float(g_Buim[base + (long)j * PP]);
        float nr = lam.x * er - lam.y * ei + br;
        float ni = lam.x * ei + lam.y * er + bi;
        er = nr; ei = ni;
    }
    g_e[c * PP + p] = make_float2(er, ei);
}

// ---------------- scan pass B: per-p scan over chunk carries ----------------
__global__ void scanB_kernel() {
    __shared__ float sr[NC], si[NC];
    int p = blockIdx.x;
    int c = threadIdx.x;
    float2 lam = g_lam[p];
    float ltr = lam.x, lti = lam.y;    // lam^64
#pragma unroll
    for (int s = 0; s < 6; s++) {
        float nr = ltr * ltr - lti * lti;
        float ni = 2.f * ltr * lti;
        ltr = nr; lti = ni;
    }
    float2 ev = g_e[c * PP + p];
    sr[c] = ev.x; si[c] = ev.y;
    __syncthreads();
    float mr = ltr, mi = lti;
    for (int off = 1; off < NC; off <<= 1) {
        float vr = 0.f, vi = 0.f;
        if (c >= off) { vr = sr[c - off]; vi = si[c - off]; }
        __syncthreads();
        if (c >= off) {
            sr[c] += mr * vr - mi * vi;
            si[c] += mr * vi + mi * vr;
        }
        __syncthreads();
        float nr = mr * mr - mi * mi;
        float ni = 2.f * mr * mi;
        mr = nr; mi = ni;
    }
    float cr = 0.f, ci = 0.f;
    if (c > 0) { cr = sr[c - 1]; ci = si[c - 1]; }
    g_carry[c * PP + p] = make_float2(cr, ci);
}

// ---------------- scan pass C: replay with carry, emit bf16 x ----------------
__global__ void scanC_kernel() {
    int p = blockIdx.x * blockDim.x + threadIdx.x;
    int c = blockIdx.y;
    float2 lam = g_lam[p];
    float2 cv = g_carry[c * PP + p];
    float xr = cv.x, xi = cv.y;
    long base = (long)c * TT * PP + p;
    for (int j = 0; j < TT; j++) {
        float br = __bfloat162float(g_Bure[base + (long)j * PP]);
        float bi = __bfloat162float(g_Buim[base + (long)j * PP]);
        float nr = lam.x * xr - lam.y * xi + br;
        float ni = lam.x * xi + lam.y * xr + bi;
        xr = nr; xi = ni;
        g_xre[base + (long)j * PP] = __float2bfloat16(xr);
        g_xim[base + (long)j * PP] = __float2bfloat16(xi);
    }
}

// =====================================================================
// GEMM 2 (mma.sync): out(L,H) = 2*bf16(bf16(xre*Cre^T) - bf16(xim*Cim^T)) + D*u
// Block 128 x 128, K=P staged by 64, 3-stage ring, 8 warps, warp 64x32 dual.
// Stage = Xr 16K + Xi 16K + Cr 16K + Ci 16K = 64KB; 3 stages = 192KB.
// =====================================================================
__global__ __launch_bounds__(256) void gemm_out_mma(const float* __restrict__ u,
                                                    const float* __restrict__ Dv,
                                                    float* __restrict__ out) {
    extern __shared__ __align__(16) unsigned char sm_[];
    const int tid = threadIdx.x;
    const int lane = tid & 31, warp = tid >> 5;
    const int warpM = warp & 1;
    const int warpN = warp >> 1;
    const int row0 = blockIdx.y * 128;   // L
    const int col0 = blockIdx.x * 128;   // H
    const uint32_t sb = s2u(sm_);

    float cRR[4][4][4] = {}, cII[4][4][4] = {};

    auto load_stage = [&](int st, int k0) {
        uint32_t base = sb + st * 65536;
#pragma unroll
        for (int i = 0; i < 4; i++) {             // Xr, Xi: 128 rows x 64 K
            int id = tid + i * 256;
            int r = id >> 3, c = id & 7;
            uint32_t o = (uint32_t)(r * 128 + ((c ^ (r & 7)) << 4));
            cpa16(base + o,         &g_xre[(size_t)(row0 + r) * PP + k0 + c * 8]);
            cpa16(base + 16384 + o, &g_xim[(size_t)(row0 + r) * PP + k0 + c * 8]);
        }
#pragma unroll
        for (int i = 0; i < 4; i++) {             // Cr, Ci: 128 rows x 64 K
            int id = tid + i * 256;
            int r = id >> 3, c = id & 7;
            uint32_t o = (uint32_t)(r * 128 + ((c ^ (r & 7)) << 4));
            cpa16(base + 32768 + o, &g_Cre[(size_t)(col0 + r) * PP + k0 + c * 8]);
            cpa16(base + 49152 + o, &g_Cim[(size_t)(col0 + r) * PP + k0 + c * 8]);
        }
        asm volatile("cp.async.commit_group;\n");
    };

    const int T = PP / 64;   // 8
    load_stage(0, 0);
    load_stage(1, 64);
    for (int t = 0; t < T; t++) {
        if (t + 1 < T) asm volatile("cp.async.wait_group 1;\n" ::: "memory");
        else           asm volatile("cp.async.wait_group 0;\n" ::: "memory");
        __syncthreads();
        if (t + 2 < T) load_stage((t + 2) % 3, (t + 2) * 64);

        uint32_t a0 = sb + (t % 3) * 65536;
#pragma unroll
        for (int kk = 0; kk < 4; kk++) {
            uint32_t axr[4][4], axi[4][4];
#pragma unroll
            for (int mt = 0; mt < 4; mt++) {
                int r = warpM * 64 + mt * 16 + (lane & 7) + ((lane >> 3) & 1) * 8;
                int c = kk * 2 + (lane >> 4);
                uint32_t off = r * 128 + ((c ^ (r & 7)) << 4);
                ldsm_x4(axr[mt], a0 + off);
                ldsm_x4(axi[mt], a0 + 16384 + off);
            }
            uint32_t bcr[2][4], bci[2][4];
#pragma unroll
            for (int pj = 0; pj < 2; pj++) {
                int g = lane >> 3;
                int n = warpN * 32 + (pj * 2 + (g >> 1)) * 8 + (lane & 7);
                int c = kk * 2 + (g & 1);
                uint32_t off = n * 128 + ((c ^ (n & 7)) << 4);
                ldsm_x4(bcr[pj], a0 + 32768 + off);
                ldsm_x4(bci[pj], a0 + 49152 + off);
            }
#pragma unroll
            for (int mt = 0; mt < 4; mt++)
#pragma unroll
                for (int nt = 0; nt < 4; nt++) {
                    mma_bf16(cRR[mt][nt], axr[mt],
                             bcr[nt >> 1][(nt & 1) * 2], bcr[nt >> 1][(nt & 1) * 2 + 1]);
                    mma_bf16(cII[mt][nt], axi[mt],
                             bci[nt >> 1][(nt & 1) * 2], bci[nt >> 1][(nt & 1) * 2 + 1]);
                }
        }
        __syncthreads();
    }

#pragma unroll
    for (int mt = 0; mt < 4; mt++) {
        int l0 = row0 + warpM * 64 + mt * 16 + (lane >> 2);
#pragma unroll
        for (int nt = 0; nt < 4; nt++) {
            int h = col0 + warpN * 32 + nt * 8 + (lane & 3) * 2;
            float2 d2 = *reinterpret_cast<const float2*>(&Dv[h]);
#pragma unroll
            for (int rw = 0; rw < 2; rw++) {
                int l = l0 + rw * 8;
                float2 u2 = *reinterpret_cast<const float2*>(&u[(size_t)l * HH + h]);
                float rr0 = bf16r(cRR[mt][nt][rw * 2 + 0]);
                float rr1 = bf16r(cRR[mt][nt][rw * 2 + 1]);
                float ii0 = bf16r(cII[mt][nt][rw * 2 + 0]);
                float ii1 = bf16r(cII[mt][nt][rw * 2 + 1]);
                float2 o;
                o.x = 2.f * bf16r(rr0 - ii0) + d2.x * u2.x;
                o.y = 2.f * bf16r(rr1 - ii1) + d2.y * u2.y;
                *reinterpret_cast<float2*>(&out[(size_t)l * HH + h]) = o;
            }
        }
    }
}

// ---------------- launch ----------------
extern "C" void kernel_launch(void* const* d_in, const int* in_sizes, int n_in,
                              void* d_out, int out_size) {
    const float* u     = (const float*)d_in[0];   // (L,H)
    const float* Lre   = (const float*)d_in[1];   // (P,)
    const float* Lim   = (const float*)d_in[2];   // (P,)
    const float* Bre   = (const float*)d_in[3];   // (P,H)
    const float* Bim   = (const float*)d_in[4];   // (P,H)
    const float* Cre   = (const float*)d_in[5];   // (H,P)
    const float* Cim   = (const float*)d_in[6];   // (H,P)
    const float* Dv    = (const float*)d_in[7];   // (H,)
    const float* lstep = (const float*)d_in[8];   // (P,1)
    float* out = (float*)d_out;

    cudaFuncSetAttribute(gemm_bu_mma,  cudaFuncAttributeMaxDynamicSharedMemorySize, 147456);
    cudaFuncSetAttribute(gemm_out_mma, cudaFuncAttributeMaxDynamicSharedMemorySize, 196608);

    prep_lambda_k<<<(PP + 255) / 256, 256>>>(Lre, Lim, lstep);
    prep_bbar_k<<<(PP * HH + 255) / 256, 256>>>(Bre, Bim);
    prep_cbf_k<<<(HH * PP + 255) / 256, 256>>>(Cre, Cim);
    prep_ubf_k<<<(LL * HH / 4 + 255) / 256, 256>>>(u);

    gemm_bu_mma<<<dim3(PP / 128, LL / 128), 256, 147456>>>();

    scanA_kernel<<<dim3(PP / 256, NC), 256>>>();
    scanB_kernel<<<PP, NC>>>();
    scanC_kernel<<<dim3(PP / 256, NC), 256>>>();

    gemm_out_mma<<<dim3(HH / 128, LL / 128), 256, 196608>>>(u, Dv, out);
}

// round 12
// speedup vs baseline: 1.0082x; 1.0082x over previous
#include <cuda_runtime.h>
#include <cuda_bf16.h>
#include <cstdint>

// Problem sizes (fixed by the reference)
#define LL 16384
#define HH 1024
#define PP 512
#define NC 256          // scan chunks
#define TT 64           // chunk length  (NC*TT == LL)

// ---------------- device scratch (static, allocation-free) ----------------
__device__ __nv_bfloat16 g_ubf [LL * HH];     // bf16(u)
__device__ __nv_bfloat16 g_Bre [PP * HH];     // bf16(Re B_bar)
__device__ __nv_bfloat16 g_Bim [PP * HH];     // bf16(Im B_bar)
__device__ __nv_bfloat16 g_Cre [HH * PP];     // bf16(C_re)
__device__ __nv_bfloat16 g_Cim [HH * PP];     // bf16(C_im)
__device__ float2        g_lam [PP];          // Lambda_bar
__device__ float2        g_scale[PP];         // (Lambda_bar-1)/Lambda
__device__ __nv_bfloat16 g_Bure[LL * PP];     // bf16(Bu_re)
__device__ __nv_bfloat16 g_Buim[LL * PP];     // bf16(Bu_im)
__device__ float2        g_e    [NC * PP];    // chunk-local end states
__device__ float2        g_carry[NC * PP];    // carry into each chunk
__device__ __nv_bfloat16 g_xre [LL * PP];     // bf16(Re x)
__device__ __nv_bfloat16 g_xim [LL * PP];     // bf16(Im x)

// ---------------- PTX helpers ----------------
__device__ __forceinline__ uint32_t s2u(const void* p) {
    return (uint32_t)__cvta_generic_to_shared(p);
}
__device__ __forceinline__ void cpa16(uint32_t dst, const void* src) {
    asm volatile("cp.async.cg.shared.global [%0], [%1], 16;\n" :: "r"(dst), "l"(src));
}
__device__ __forceinline__ void ldsm_x4(uint32_t* r, uint32_t addr) {
    asm volatile("ldmatrix.sync.aligned.m8n8.x4.shared.b16 {%0,%1,%2,%3}, [%4];\n"
                 : "=r"(r[0]), "=r"(r[1]), "=r"(r[2]), "=r"(r[3]) : "r"(addr));
}
__device__ __forceinline__ void mma_bf16(float* c, const uint32_t* a, uint32_t b0, uint32_t b1) {
    asm volatile(
        "mma.sync.aligned.m16n8k16.row.col.f32.bf16.bf16.f32 "
        "{%0,%1,%2,%3}, {%4,%5,%6,%7}, {%8,%9}, {%0,%1,%2,%3};\n"
        : "+f"(c[0]), "+f"(c[1]), "+f"(c[2]), "+f"(c[3])
        : "r"(a[0]), "r"(a[1]), "r"(a[2]), "r"(a[3]), "r"(b0), "r"(b1));
}
__device__ __forceinline__ uint32_t packbf2(float x, float y) {
    __nv_bfloat162 v = __floats2bfloat162_rn(x, y);
    return *reinterpret_cast<uint32_t*>(&v);
}
__device__ __forceinline__ float bf16r(float x) {
    return __bfloat162float(__float2bfloat16(x));
}

// ---------------- prep kernels ----------------
__global__ void prep_lambda_k(const float* __restrict__ Lre,
                              const float* __restrict__ Lim,
                              const float* __restrict__ lstep) {
    int p = blockIdx.x * blockDim.x + threadIdx.x;
    if (p >= PP) return;
    float dt = expf(lstep[p]);
    float lr = Lre[p], li = Lim[p];
    float ar = lr * dt, ai = li * dt;
    float m  = expf(ar);
    float lbr = m * cosf(ai);
    float lbi = m * sinf(ai);
    g_lam[p] = make_float2(lbr, lbi);
    float d  = lr * lr + li * li;
    float nr = lbr - 1.0f;
    float sr = (nr * lr + lbi * li) / d;
    float si = (lbi * lr - nr * li) / d;
    g_scale[p] = make_float2(sr, si);
}

__global__ void prep_bbar_k(const float* __restrict__ Bre,
                            const float* __restrict__ Bim) {
    int i = blockIdx.x * blockDim.x + threadIdx.x;
    if (i >= PP * HH) return;
    int p = i / HH;
    float2 s = g_scale[p];
    float br = Bre[i], bi = Bim[i];
    g_Bre[i] = __float2bfloat16(s.x * br - s.y * bi);
    g_Bim[i] = __float2bfloat16(s.x * bi + s.y * br);
}

__global__ void prep_cbf_k(const float* __restrict__ Cre,
                           const float* __restrict__ Cim) {
    int i = blockIdx.x * blockDim.x + threadIdx.x;
    if (i >= HH * PP) return;
    g_Cre[i] = __float2bfloat16(Cre[i]);
    g_Cim[i] = __float2bfloat16(Cim[i]);
}

__global__ void prep_ubf_k(const float* __restrict__ u) {
    int i = blockIdx.x * blockDim.x + threadIdx.x;
    int base = i * 4;
    if (base >= LL * HH) return;
    float4 v = *reinterpret_cast<const float4*>(&u[base]);
    g_ubf[base + 0] = __float2bfloat16(v.x);
    g_ubf[base + 1] = __float2bfloat16(v.y);
    g_ubf[base + 2] = __float2bfloat16(v.z);
    g_ubf[base + 3] = __float2bfloat16(v.w);
}

// =====================================================================
// GEMM 1 (mma.sync): Bu(L,P) = ubf(L,H) x {Bre,Bim}(P,H)^T, dual output.
// Block 128(M) x 128(N), K staged by 64, 2-stage cp.async, 16 warps (4Mx4N).
// Warp tile: 32(M) x 32(N), both outputs (proven R6 fragment mapping).
// Stage = A 16K + Br 16K + Bi 16K = 48KB; 2 stages = 96KB -> 2 CTAs/SM.
// =====================================================================
__global__ __launch_bounds__(512) void gemm_bu_mma() {
    extern __shared__ __align__(16) unsigned char sm_[];
    const int tid = threadIdx.x;
    const int lane = tid & 31, warp = tid >> 5;
    const int warpM = warp & 3;          // 4 warps over M
    const int warpN = warp >> 2;         // 4 warps over N
    const int row0 = blockIdx.y * 128;   // L
    const int col0 = blockIdx.x * 128;   // P
    const uint32_t sb = s2u(sm_);

    float cR[2][4][4] = {}, cI[2][4][4] = {};

    auto load_stage = [&](int st, int k0) {
        uint32_t base = sb + st * 49152;
#pragma unroll
        for (int i = 0; i < 2; i++) {             // A: 128 rows x 64 K = 1024 chunks
            int id = tid + i * 512;
            int r = id >> 3, c = id & 7;
            uint32_t o = (uint32_t)(r * 128 + ((c ^ (r & 7)) << 4));
            cpa16(base + o, &g_ubf[(size_t)(row0 + r) * HH + k0 + c * 8]);
        }
#pragma unroll
        for (int i = 0; i < 2; i++) {             // Br, Bi: 128 rows x 64 K each
            int id = tid + i * 512;
            int r = id >> 3, c = id & 7;
            uint32_t o = (uint32_t)(r * 128 + ((c ^ (r & 7)) << 4));
            cpa16(base + 16384 + o, &g_Bre[(size_t)(col0 + r) * HH + k0 + c * 8]);
            cpa16(base + 32768 + o, &g_Bim[(size_t)(col0 + r) * HH + k0 + c * 8]);
        }
        asm volatile("cp.async.commit_group;\n");
    };

    load_stage(0, 0);
    const int T = HH / 64;   // 16
    for (int t = 0; t < T; t++) {
        if (t + 1 < T) {
            load_stage((t + 1) & 1, (t + 1) * 64);
            asm volatile("cp.async.wait_group 1;\n" ::: "memory");
        } else {
            asm volatile("cp.async.wait_group 0;\n" ::: "memory");
        }
        __syncthreads();
        uint32_t a0 = sb + (t & 1) * 49152;
#pragma unroll
        for (int kk = 0; kk < 4; kk++) {
            uint32_t af[2][4];
#pragma unroll
            for (int mt = 0; mt < 2; mt++) {
                int r = warpM * 32 + mt * 16 + (lane & 7) + ((lane >> 3) & 1) * 8;
                int c = kk * 2 + (lane >> 4);
                ldsm_x4(af[mt], a0 + r * 128 + ((c ^ (r & 7)) << 4));
            }
            uint32_t bR[2][4], bI[2][4];   // pair pj covers n8 tiles 2pj, 2pj+1
#pragma unroll
            for (int pj = 0; pj < 2; pj++) {
                int g = lane >> 3;
                int n = warpN * 32 + (pj * 2 + (g >> 1)) * 8 + (lane & 7);
                int c = kk * 2 + (g & 1);
                uint32_t off = n * 128 + ((c ^ (n & 7)) << 4);
                ldsm_x4(bR[pj], a0 + 16384 + off);
                ldsm_x4(bI[pj], a0 + 32768 + off);
            }
#pragma unroll
            for (int mt = 0; mt < 2; mt++)
#pragma unroll
                for (int nt = 0; nt < 4; nt++) {
                    mma_bf16(cR[mt][nt], af[mt],
                             bR[nt >> 1][(nt & 1) * 2], bR[nt >> 1][(nt & 1) * 2 + 1]);
                    mma_bf16(cI[mt][nt], af[mt],
                             bI[nt >> 1][(nt & 1) * 2], bI[nt >> 1][(nt & 1) * 2 + 1]);
                }
        }
        __syncthreads();
    }

#pragma unroll
    for (int mt = 0; mt < 2; mt++) {
        int l0 = row0 + warpM * 32 + mt * 16 + (lane >> 2);
#pragma unroll
        for (int nt = 0; nt < 4; nt++) {
            int p = col0 + warpN * 32 + nt * 8 + (lane & 3) * 2;
            *reinterpret_cast<uint32_t*>(&g_Bure[(size_t)l0 * PP + p])       = packbf2(cR[mt][nt][0], cR[mt][nt][1]);
            *reinterpret_cast<uint32_t*>(&g_Bure[(size_t)(l0 + 8) * PP + p]) = packbf2(cR[mt][nt][2], cR[mt][nt][3]);
            *reinterpret_cast<uint32_t*>(&g_Buim[(size_t)l0 * PP + p])       = packbf2(cI[mt][nt][0], cI[mt][nt][1]);
            *reinterpret_cast<uint32_t*>(&g_Buim[(size_t)(l0 + 8) * PP + p]) = packbf2(cI[mt][nt][2], cI[mt][nt][3]);
        }
    }
}

// ---------------- scan pass A: chunk-local end states ----------------
__global__ void scanA_kernel() {
    int p = blockIdx.x * blockDim.x + threadIdx.x;
    int c = blockIdx.y;
    float2 lam = g_lam[p];
    float er = 0.f, ei = 0.f;
    long base = (long)c * TT * PP + p;
    for (int j = 0; j < TT; j++) {
        float br = __bfloat162float(g_Bure[base + (long)j * PP]);
        float bi = __bfloat162float(g_Buim[base + (long)j * PP]);
        float nr = lam.x * er - lam.y * ei + br;
        float ni = lam.x * ei + lam.y * er + bi;
        er = nr; ei = ni;
    }
    g_e[c * PP + p] = make_float2(er, ei);
}

// ---------------- scan pass B: per-p scan over chunk carries ----------------
__global__ void scanB_kernel() {
    __shared__ float sr[NC], si[NC];
    int p = blockIdx.x;
    int c = threadIdx.x;
    float2 lam = g_lam[p];
    float ltr = lam.x, lti = lam.y;    // lam^64
#pragma unroll
    for (int s = 0; s < 6; s++) {
        float nr = ltr * ltr - lti * lti;
        float ni = 2.f * ltr * lti;
        ltr = nr; lti = ni;
    }
    float2 ev = g_e[c * PP + p];
    sr[c] = ev.x; si[c] = ev.y;
    __syncthreads();
    float mr = ltr, mi = lti;
    for (int off = 1; off < NC; off <<= 1) {
        float vr = 0.f, vi = 0.f;
        if (c >= off) { vr = sr[c - off]; vi = si[c - off]; }
        __syncthreads();
        if (c >= off) {
            sr[c] += mr * vr - mi * vi;
            si[c] += mr * vi + mi * vr;
        }
        __syncthreads();
        float nr = mr * mr - mi * mi;
        float ni = 2.f * mr * mi;
        mr = nr; mi = ni;
    }
    float cr = 0.f, ci = 0.f;
    if (c > 0) { cr = sr[c - 1]; ci = si[c - 1]; }
    g_carry[c * PP + p] = make_float2(cr, ci);
}

// ---------------- scan pass C: replay with carry, emit bf16 x ----------------
__global__ void scanC_kernel() {
    int p = blockIdx.x * blockDim.x + threadIdx.x;
    int c = blockIdx.y;
    float2 lam = g_lam[p];
    float2 cv = g_carry[c * PP + p];
    float xr = cv.x, xi = cv.y;
    long base = (long)c * TT * PP + p;
    for (int j = 0; j < TT; j++) {
        float br = __bfloat162float(g_Bure[base + (long)j * PP]);
        float bi = __bfloat162float(g_Buim[base + (long)j * PP]);
        float nr = lam.x * xr - lam.y * xi + br;
        float ni = lam.x * xi + lam.y * xr + bi;
        xr = nr; xi = ni;
        g_xre[base + (long)j * PP] = __float2bfloat16(xr);
        g_xim[base + (long)j * PP] = __float2bfloat16(xi);
    }
}

// =====================================================================
// GEMM 2 (mma.sync): out(L,H) = 2*bf16(bf16(xre*Cre^T) - bf16(xim*Cim^T)) + D*u
// Block 128 x 128, K=P staged by 64, 2-stage, 16 warps (4Mx4N), warp 32x32 dual.
// Stage = Xr 16K + Xi 16K + Cr 16K + Ci 16K = 64KB; 2 stages = 128KB.
// =====================================================================
__global__ __launch_bounds__(512) void gemm_out_mma(const float* __restrict__ u,
                                                    const float* __restrict__ Dv,
                                                    float* __restrict__ out) {
    extern __shared__ __align__(16) unsigned char sm_[];
    const int tid = threadIdx.x;
    const int lane = tid & 31, warp = tid >> 5;
    const int warpM = warp & 3;
    const int warpN = warp >> 2;
    const int row0 = blockIdx.y * 128;   // L
    const int col0 = blockIdx.x * 128;   // H
    const uint32_t sb = s2u(sm_);

    float cRR[2][4][4] = {}, cII[2][4][4] = {};

    auto load_stage = [&](int st, int k0) {
        uint32_t base = sb + st * 65536;
#pragma unroll
        for (int i = 0; i < 2; i++) {             // Xr, Xi: 128 rows x 64 K
            int id = tid + i * 512;
            int r = id >> 3, c = id & 7;
            uint32_t o = (uint32_t)(r * 128 + ((c ^ (r & 7)) << 4));
            cpa16(base + o,         &g_xre[(size_t)(row0 + r) * PP + k0 + c * 8]);
            cpa16(base + 16384 + o, &g_xim[(size_t)(row0 + r) * PP + k0 + c * 8]);
        }
#pragma unroll
        for (int i = 0; i < 2; i++) {             // Cr, Ci: 128 rows x 64 K
            int id = tid + i * 512;
            int r = id >> 3, c = id & 7;
            uint32_t o = (uint32_t)(r * 128 + ((c ^ (r & 7)) << 4));
            cpa16(base + 32768 + o, &g_Cre[(size_t)(col0 + r) * PP + k0 + c * 8]);
            cpa16(base + 49152 + o, &g_Cim[(size_t)(col0 + r) * PP + k0 + c * 8]);
        }
        asm volatile("cp.async.commit_group;\n");
    };

    load_stage(0, 0);
    const int T = PP / 64;   // 8
    for (int t = 0; t < T; t++) {
        if (t + 1 < T) {
            load_stage((t + 1) & 1, (t + 1) * 64);
            asm volatile("cp.async.wait_group 1;\n" ::: "memory");
        } else {
            asm volatile("cp.async.wait_group 0;\n" ::: "memory");
        }
        __syncthreads();
        uint32_t a0 = sb + (t & 1) * 65536;
#pragma unroll
        for (int kk = 0; kk < 4; kk++) {
            uint32_t axr[2][4], axi[2][4];
#pragma unroll
            for (int mt = 0; mt < 2; mt++) {
                int r = warpM * 32 + mt * 16 + (lane & 7) + ((lane >> 3) & 1) * 8;
                int c = kk * 2 + (lane >> 4);
                uint32_t off = r * 128 + ((c ^ (r & 7)) << 4);
                ldsm_x4(axr[mt], a0 + off);
                ldsm_x4(axi[mt], a0 + 16384 + off);
            }
            uint32_t bcr[2][4], bci[2][4];
#pragma unroll
            for (int pj = 0; pj < 2; pj++) {
                int g = lane >> 3;
                int n = warpN * 32 + (pj * 2 + (g >> 1)) * 8 + (lane & 7);
                int c = kk * 2 + (g & 1);
                uint32_t off = n * 128 + ((c ^ (n & 7)) << 4);
                ldsm_x4(bcr[pj], a0 + 32768 + off);
                ldsm_x4(bci[pj], a0 + 49152 + off);
            }
#pragma unroll
            for (int mt = 0; mt < 2; mt++)
#pragma unroll
                for (int nt = 0; nt < 4; nt++) {
                    mma_bf16(cRR[mt][nt], axr[mt],
                             bcr[nt >> 1][(nt & 1) * 2], bcr[nt >> 1][(nt & 1) * 2 + 1]);
                    mma_bf16(cII[mt][nt], axi[mt],
                             bci[nt >> 1][(nt & 1) * 2], bci[nt >> 1][(nt & 1) * 2 + 1]);
                }
        }
        __syncthreads();
    }

#pragma unroll
    for (int mt = 0; mt < 2; mt++) {
        int l0 = row0 + warpM * 32 + mt * 16 + (lane >> 2);
#pragma unroll
        for (int nt = 0; nt < 4; nt++) {
            int h = col0 + warpN * 32 + nt * 8 + (lane & 3) * 2;
            float2 d2 = *reinterpret_cast<const float2*>(&Dv[h]);
#pragma unroll
            for (int rw = 0; rw < 2; rw++) {
                int l = l0 + rw * 8;
                float2 u2 = *reinterpret_cast<const float2*>(&u[(size_t)l * HH + h]);
                float rr0 = bf16r(cRR[mt][nt][rw * 2 + 0]);
                float rr1 = bf16r(cRR[mt][nt][rw * 2 + 1]);
                float ii0 = bf16r(cII[mt][nt][rw * 2 + 0]);
                float ii1 = bf16r(cII[mt][nt][rw * 2 + 1]);
                float2 o;
                o.x = 2.f * bf16r(rr0 - ii0) + d2.x * u2.x;
                o.y = 2.f * bf16r(rr1 - ii1) + d2.y * u2.y;
                *reinterpret_cast<float2*>(&out[(size_t)l * HH + h]) = o;
            }
        }
    }
}

// ---------------- launch ----------------
extern "C" void kernel_launch(void* const* d_in, const int* in_sizes, int n_in,
                              void* d_out, int out_size) {
    const float* u     = (const float*)d_in[0];   // (L,H)
    const float* Lre   = (const float*)d_in[1];   // (P,)
    const float* Lim   = (const float*)d_in[2];   // (P,)
    const float* Bre   = (const float*)d_in[3];   // (P,H)
    const float* Bim   = (const float*)d_in[4];   // (P,H)
    const float* Cre   = (const float*)d_in[5];   // (H,P)
    const float* Cim   = (const float*)d_in[6];   // (H,P)
    const float* Dv    = (const float*)d_in[7];   // (H,)
    const float* lstep = (const float*)d_in[8];   // (P,1)
    float* out = (float*)d_out;

    cudaFuncSetAttribute(gemm_bu_mma,  cudaFuncAttributeMaxDynamicSharedMemorySize, 98304);
    cudaFuncSetAttribute(gemm_out_mma, cudaFuncAttributeMaxDynamicSharedMemorySize, 131072);

    prep_lambda_k<<<(PP + 255) / 256, 256>>>(Lre, Lim, lstep);
    prep_bbar_k<<<(PP * HH + 255) / 256, 256>>>(Bre, Bim);
    prep_cbf_k<<<(HH * PP + 255) / 256, 256>>>(Cre, Cim);
    prep_ubf_k<<<(LL * HH / 4 + 255) / 256, 256>>>(u);

    gemm_bu_mma<<<dim3(PP / 128, LL / 128), 512, 98304>>>();

    scanA_kernel<<<dim3(PP / 256, NC), 256>>>();
    scanB_kernel<<<PP, NC>>>();
    scanC_kernel<<<dim3(PP / 256, NC), 256>>>();

    gemm_out_mma<<<dim3(HH / 128, LL / 128), 512, 131072>>>(u, Dv, out);
}

// round 13
// speedup vs baseline: 1.6541x; 1.6406x over previous
#include <cuda_runtime.h>
#include <cuda_bf16.h>
#include <cstdint>

// Problem sizes (fixed by the reference)
#define LL 16384
#define HH 1024
#define PP 512
#define NC 256          // scan chunks
#define TT 64           // chunk length  (NC*TT == LL)

// ---------------- device scratch (static, allocation-free) ----------------
__device__ __nv_bfloat16 g_ubf [LL * HH];     // bf16(u)
__device__ __nv_bfloat16 g_Bre [PP * HH];     // bf16(Re B_bar)
__device__ __nv_bfloat16 g_Bim [PP * HH];     // bf16(Im B_bar)
__device__ __nv_bfloat16 g_Cre [HH * PP];     // bf16(C_re)
__device__ __nv_bfloat16 g_Cim [HH * PP];     // bf16(C_im)
__device__ float2        g_lam [PP];          // Lambda_bar
__device__ float2        g_scale[PP];         // (Lambda_bar-1)/Lambda
__device__ __nv_bfloat16 g_Bure[LL * PP];     // bf16(Bu_re)
__device__ __nv_bfloat16 g_Buim[LL * PP];     // bf16(Bu_im)
__device__ float2        g_e    [NC * PP];    // chunk-local end states
__device__ float2        g_carry[NC * PP];    // carry into each chunk
__device__ __nv_bfloat16 g_xre [LL * PP];     // bf16(Re x)
__device__ __nv_bfloat16 g_xim [LL * PP];     // bf16(Im x)

// ---------------- PTX helpers ----------------
__device__ __forceinline__ uint32_t s2u(const void* p) {
    return (uint32_t)__cvta_generic_to_shared(p);
}
__device__ __forceinline__ void cpa16(uint32_t dst, const void* src) {
    asm volatile("cp.async.cg.shared.global [%0], [%1], 16;\n" :: "r"(dst), "l"(src));
}
__device__ __forceinline__ void ldsm_x4(uint32_t* r, uint32_t addr) {
    asm volatile("ldmatrix.sync.aligned.m8n8.x4.shared.b16 {%0,%1,%2,%3}, [%4];\n"
                 : "=r"(r[0]), "=r"(r[1]), "=r"(r[2]), "=r"(r[3]) : "r"(addr));
}
__device__ __forceinline__ void mma_bf16(float* c, const uint32_t* a, uint32_t b0, uint32_t b1) {
    asm volatile(
        "mma.sync.aligned.m16n8k16.row.col.f32.bf16.bf16.f32 "
        "{%0,%1,%2,%3}, {%4,%5,%6,%7}, {%8,%9}, {%0,%1,%2,%3};\n"
        : "+f"(c[0]), "+f"(c[1]), "+f"(c[2]), "+f"(c[3])
        : "r"(a[0]), "r"(a[1]), "r"(a[2]), "r"(a[3]), "r"(b0), "r"(b1));
}
__device__ __forceinline__ uint32_t packbf2(float x, float y) {
    __nv_bfloat162 v = __floats2bfloat162_rn(x, y);
    return *reinterpret_cast<uint32_t*>(&v);
}
__device__ __forceinline__ float bf16r(float x) {
    return __bfloat162float(__float2bfloat16(x));
}

// ---------------- prep kernels ----------------
__global__ void prep_lambda_k(const float* __restrict__ Lre,
                              const float* __restrict__ Lim,
                              const float* __restrict__ lstep) {
    int p = blockIdx.x * blockDim.x + threadIdx.x;
    if (p >= PP) return;
    float dt = expf(lstep[p]);
    float lr = Lre[p], li = Lim[p];
    float ar = lr * dt, ai = li * dt;
    float m  = expf(ar);
    float lbr = m * cosf(ai);
    float lbi = m * sinf(ai);
    g_lam[p] = make_float2(lbr, lbi);
    float d  = lr * lr + li * li;
    float nr = lbr - 1.0f;
    float sr = (nr * lr + lbi * li) / d;
    float si = (lbi * lr - nr * li) / d;
    g_scale[p] = make_float2(sr, si);
}

__global__ void prep_bbar_k(const float* __restrict__ Bre,
                            const float* __restrict__ Bim) {
    int i = blockIdx.x * blockDim.x + threadIdx.x;
    if (i >= PP * HH) return;
    int p = i / HH;
    float2 s = g_scale[p];
    float br = Bre[i], bi = Bim[i];
    g_Bre[i] = __float2bfloat16(s.x * br - s.y * bi);
    g_Bim[i] = __float2bfloat16(s.x * bi + s.y * br);
}

__global__ void prep_cbf_k(const float* __restrict__ Cre,
                           const float* __restrict__ Cim) {
    int i = blockIdx.x * blockDim.x + threadIdx.x;
    if (i >= HH * PP) return;
    g_Cre[i] = __float2bfloat16(Cre[i]);
    g_Cim[i] = __float2bfloat16(Cim[i]);
}

__global__ void prep_ubf_k(const float* __restrict__ u) {
    int i = blockIdx.x * blockDim.x + threadIdx.x;
    int base = i * 4;
    if (base >= LL * HH) return;
    float4 v = *reinterpret_cast<const float4*>(&u[base]);
    g_ubf[base + 0] = __float2bfloat16(v.x);
    g_ubf[base + 1] = __float2bfloat16(v.y);
    g_ubf[base + 2] = __float2bfloat16(v.z);
    g_ubf[base + 3] = __float2bfloat16(v.w);
}

// =====================================================================
// GEMM 1 (mma.sync): Bu(L,P) = ubf(L,H) x {Bre,Bim}(P,H)^T, dual output.
// Block 128(M) x 64(N), K staged by 64, 3-stage cp.async ring, 8 warps.
// Warp tile 32x32, both outputs (proven R6 fragment mapping).
// Stage = A 16K + Br 8K + Bi 8K = 32KB; 3 stages = 96KB -> 2 CTAs/SM.
// Single __syncthreads per K-stage.
// =====================================================================
__global__ __launch_bounds__(256) void gemm_bu_mma() {
    extern __shared__ __align__(16) unsigned char sm_[];
    const int tid = threadIdx.x;
    const int lane = tid & 31, warp = tid >> 5;
    const int warpM = warp & 3, warpN = warp >> 2;
    const int row0 = blockIdx.y * 128;   // L
    const int col0 = blockIdx.x * 64;    // P
    const uint32_t sb = s2u(sm_);

    float cR[2][4][4] = {}, cI[2][4][4] = {};

    auto load_stage = [&](int st, int k0) {
        uint32_t base = sb + st * 32768;
#pragma unroll
        for (int i = 0; i < 4; i++) {             // A: 128x64 bf16 = 1024 chunks
            int id = tid + i * 256;
            int r = id >> 3, c = id & 7;
            cpa16(base + r * 128 + ((c ^ (r & 7)) << 4),
                  &g_ubf[(size_t)(row0 + r) * HH + k0 + c * 8]);
        }
#pragma unroll
        for (int i = 0; i < 2; i++) {             // B tiles: 64x64 each
            int id = tid + i * 256;
            int r = id >> 3, c = id & 7;
            uint32_t off = base + 16384 + r * 128 + ((c ^ (r & 7)) << 4);
            cpa16(off,        &g_Bre[(size_t)(col0 + r) * HH + k0 + c * 8]);
            cpa16(off + 8192, &g_Bim[(size_t)(col0 + r) * HH + k0 + c * 8]);
        }
        asm volatile("cp.async.commit_group;\n");
    };

    const int T = HH / 64;   // 16
    load_stage(0, 0);
    load_stage(1, 64);
    for (int t = 0; t < T; t++) {
        if (t + 1 < T) asm volatile("cp.async.wait_group 1;\n" ::: "memory");
        else           asm volatile("cp.async.wait_group 0;\n" ::: "memory");
        __syncthreads();
        if (t + 2 < T) load_stage((t + 2) % 3, (t + 2) * 64);

        uint32_t a0 = sb + (t % 3) * 32768;
#pragma unroll
        for (int kk = 0; kk < 4; kk++) {
            uint32_t af[2][4];
#pragma unroll
            for (int mt = 0; mt < 2; mt++) {
                int r = warpM * 32 + mt * 16 + (lane & 7) + ((lane >> 3) & 1) * 8;
                int c = kk * 2 + (lane >> 4);
                ldsm_x4(af[mt], a0 + r * 128 + ((c ^ (r & 7)) << 4));
            }
            uint32_t bR[2][4], bI[2][4];   // pair pj covers n8 tiles 2pj, 2pj+1
#pragma unroll
            for (int pj = 0; pj < 2; pj++) {
                int g = lane >> 3;
                int n = warpN * 32 + (pj * 2 + (g >> 1)) * 8 + (lane & 7);
                int c = kk * 2 + (g & 1);
                uint32_t off = n * 128 + ((c ^ (n & 7)) << 4);
                ldsm_x4(bR[pj], a0 + 16384 + off);
                ldsm_x4(bI[pj], a0 + 24576 + off);
            }
#pragma unroll
            for (int mt = 0; mt < 2; mt++)
#pragma unroll
                for (int nt = 0; nt < 4; nt++) {
                    mma_bf16(cR[mt][nt], af[mt],
                             bR[nt >> 1][(nt & 1) * 2], bR[nt >> 1][(nt & 1) * 2 + 1]);
                    mma_bf16(cI[mt][nt], af[mt],
                             bI[nt >> 1][(nt & 1) * 2], bI[nt >> 1][(nt & 1) * 2 + 1]);
                }
        }
    }

#pragma unroll
    for (int mt = 0; mt < 2; mt++) {
        int l0 = row0 + warpM * 32 + mt * 16 + (lane >> 2);
#pragma unroll
        for (int nt = 0; nt < 4; nt++) {
            int p = col0 + warpN * 32 + nt * 8 + (lane & 3) * 2;
            *reinterpret_cast<uint32_t*>(&g_Bure[(size_t)l0 * PP + p])       = packbf2(cR[mt][nt][0], cR[mt][nt][1]);
            *reinterpret_cast<uint32_t*>(&g_Bure[(size_t)(l0 + 8) * PP + p]) = packbf2(cR[mt][nt][2], cR[mt][nt][3]);
            *reinterpret_cast<uint32_t*>(&g_Buim[(size_t)l0 * PP + p])       = packbf2(cI[mt][nt][0], cI[mt][nt][1]);
            *reinterpret_cast<uint32_t*>(&g_Buim[(size_t)(l0 + 8) * PP + p]) = packbf2(cI[mt][nt][2], cI[mt][nt][3]);
        }
    }
}

// ---------------- scan pass A: chunk-local end states ----------------
__global__ void scanA_kernel() {
    int p = blockIdx.x * blockDim.x + threadIdx.x;   // 0..PP-1
    int c = blockIdx.y;                              // chunk
    float2 lam = g_lam[p];
    float er = 0.f, ei = 0.f;
    long base = (long)c * TT * PP + p;
    for (int j = 0; j < TT; j++) {
        float br = __bfloat162float(g_Bure[base + (long)j * PP]);
        float bi = __bfloat162float(g_Buim[base + (long)j * PP]);
        float nr = lam.x * er - lam.y * ei + br;
        float ni = lam.x * ei + lam.y * er + bi;
        er = nr; ei = ni;
    }
    g_e[c * PP + p] = make_float2(er, ei);
}

// ---------------- scan pass B: per-p scan over chunk carries ----------------
__global__ void scanB_kernel() {
    __shared__ float sr[NC], si[NC];
    int p = blockIdx.x;
    int c = threadIdx.x;
    float2 lam = g_lam[p];
    float ltr = lam.x, lti = lam.y;    // lam^64
#pragma unroll
    for (int s = 0; s < 6; s++) {
        float nr = ltr * ltr - lti * lti;
        float ni = 2.f * ltr * lti;
        ltr = nr; lti = ni;
    }
    float2 ev = g_e[c * PP + p];
    sr[c] = ev.x; si[c] = ev.y;
    __syncthreads();
    float mr = ltr, mi = lti;
    for (int off = 1; off < NC; off <<= 1) {
        float vr = 0.f, vi = 0.f;
        if (c >= off) { vr = sr[c - off]; vi = si[c - off]; }
        __syncthreads();
        if (c >= off) {
            sr[c] += mr * vr - mi * vi;
            si[c] += mr * vi + mi * vr;
        }
        __syncthreads();
        float nr = mr * mr - mi * mi;
        float ni = 2.f * mr * mi;
        mr = nr; mi = ni;
    }
    float cr = 0.f, ci = 0.f;
    if (c > 0) { cr = sr[c - 1]; ci = si[c - 1]; }
    g_carry[c * PP + p] = make_float2(cr, ci);
}

// ---------------- scan pass C: replay with carry, emit bf16 x ----------------
__global__ void scanC_kernel() {
    int p = blockIdx.x * blockDim.x + threadIdx.x;
    int c = blockIdx.y;
    float2 lam = g_lam[p];
    float2 cv = g_carry[c * PP + p];
    float xr = cv.x, xi = cv.y;
    long base = (long)c * TT * PP + p;
    for (int j = 0; j < TT; j++) {
        float br = __bfloat162float(g_Bure[base + (long)j * PP]);
        float bi = __bfloat162float(g_Buim[base + (long)j * PP]);
        float nr = lam.x * xr - lam.y * xi + br;
        float ni = lam.x * xi + lam.y * xr + bi;
        xr = nr; xi = ni;
        g_xre[base + (long)j * PP] = __float2bfloat16(xr);
        g_xim[base + (long)j * PP] = __float2bfloat16(xi);
    }
}

// =====================================================================
// GEMM 2 (mma.sync): out(L,H) = 2*bf16(bf16(xre*Cre^T) - bf16(xim*Cim^T)) + D*u
// Block 128 x 64, K=P staged by 64, 2-stage (proven R6 config), 8 warps.
// Stage = Xr 16K + Xi 16K + Cr 8K + Ci 8K = 48KB, x2 = 96KB -> 2 CTAs/SM.
// =====================================================================
__global__ __launch_bounds__(256) void gemm_out_mma(const float* __restrict__ u,
                                                    const float* __restrict__ Dv,
                                                    float* __restrict__ out) {
    extern __shared__ __align__(16) unsigned char sm_[];
    const int tid = threadIdx.x;
    const int lane = tid & 31, warp = tid >> 5;
    const int warpM = warp & 3, warpN = warp >> 2;
    const int row0 = blockIdx.y * 128;   // L
    const int col0 = blockIdx.x * 64;    // H
    const uint32_t sb = s2u(sm_);

    float cRR[2][4][4] = {}, cII[2][4][4] = {};

    auto load_stage = [&](int st, int k0) {
        uint32_t base = sb + st * 49152;
#pragma unroll
        for (int i = 0; i < 4; i++) {             // Xr, Xi: 128x64 each
            int id = tid + i * 256;
            int r = id >> 3, c = id & 7;
            uint32_t off = base + r * 128 + ((c ^ (r & 7)) << 4);
            cpa16(off,         &g_xre[(size_t)(row0 + r) * PP + k0 + c * 8]);
            cpa16(off + 16384, &g_xim[(size_t)(row0 + r) * PP + k0 + c * 8]);
        }
#pragma unroll
        for (int i = 0; i < 2; i++) {             // Cr, Ci: 64x64 each
            int id = tid + i * 256;
            int r = id >> 3, c = id & 7;
            uint32_t off = base + 32768 + r * 128 + ((c ^ (r & 7)) << 4);
            cpa16(off,        &g_Cre[(size_t)(col0 + r) * PP + k0 + c * 8]);
            cpa16(off + 8192, &g_Cim[(size_t)(col0 + r) * PP + k0 + c * 8]);
        }
        asm volatile("cp.async.commit_group;\n");
    };

    load_stage(0, 0);
    const int T = PP / 64;   // 8
    for (int t = 0; t < T; t++) {
        if (t + 1 < T) {
            load_stage((t + 1) & 1, (t + 1) * 64);
            asm volatile("cp.async.wait_group 1;\n" ::: "memory");
        } else {
            asm volatile("cp.async.wait_group 0;\n" ::: "memory");
        }
        __syncthreads();
        uint32_t a0 = sb + (t & 1) * 49152;
#pragma unroll
        for (int kk = 0; kk < 4; kk++) {
            uint32_t axr[2][4], axi[2][4];
#pragma unroll
            for (int mt = 0; mt < 2; mt++) {
                int r = warpM * 32 + mt * 16 + (lane & 7) + ((lane >> 3) & 1) * 8;
                int c = kk * 2 + (lane >> 4);
                uint32_t off = r * 128 + ((c ^ (r & 7)) << 4);
                ldsm_x4(axr[mt], a0 + off);
                ldsm_x4(axi[mt], a0 + 16384 + off);
            }
            uint32_t bcr[2][4], bci[2][4];
#pragma unroll
            for (int pj = 0; pj < 2; pj++) {
                int g = lane >> 3;
                int n = warpN * 32 + (pj * 2 + (g >> 1)) * 8 + (lane & 7);
                int c = kk * 2 + (g & 1);
                uint32_t off = n * 128 + ((c ^ (n & 7)) << 4);
                ldsm_x4(bcr[pj], a0 + 32768 + off);
                ldsm_x4(bci[pj], a0 + 40960 + off);
            }
#pragma unroll
            for (int mt = 0; mt < 2; mt++)
#pragma unroll
                for (int nt = 0; nt < 4; nt++) {
                    mma_bf16(cRR[mt][nt], axr[mt],
                             bcr[nt >> 1][(nt & 1) * 2], bcr[nt >> 1][(nt & 1) * 2 + 1]);
                    mma_bf16(cII[mt][nt], axi[mt],
                             bci[nt >> 1][(nt & 1) * 2], bci[nt >> 1][(nt & 1) * 2 + 1]);
                }
        }
        __syncthreads();
    }

#pragma unroll
    for (int mt = 0; mt < 2; mt++) {
        int l0 = row0 + warpM * 32 + mt * 16 + (lane >> 2);
#pragma unroll
        for (int nt = 0; nt < 4; nt++) {
            int h = col0 + warpN * 32 + nt * 8 + (lane & 3) * 2;
            float2 d2 = *reinterpret_cast<const float2*>(&Dv[h]);
#pragma unroll
            for (int rw = 0; rw < 2; rw++) {
                int l = l0 + rw * 8;
                float2 u2 = *reinterpret_cast<const float2*>(&u[(size_t)l * HH + h]);
                float rr0 = bf16r(cRR[mt][nt][rw * 2 + 0]);
                float rr1 = bf16r(cRR[mt][nt][rw * 2 + 1]);
                float ii0 = bf16r(cII[mt][nt][rw * 2 + 0]);
                float ii1 = bf16r(cII[mt][nt][rw * 2 + 1]);
                float2 o;
                o.x = 2.f * bf16r(rr0 - ii0) + d2.x * u2.x;
                o.y = 2.f * bf16r(rr1 - ii1) + d2.y * u2.y;
                *reinterpret_cast<float2*>(&out[(size_t)l * HH + h]) = o;
            }
        }
    }
}

// ---------------- launch ----------------
extern "C" void kernel_launch(void* const* d_in, const int* in_sizes, int n_in,
                              void* d_out, int out_size) {
    const float* u     = (const float*)d_in[0];   // (L,H)
    const float* Lre   = (const float*)d_in[1];   // (P,)
    const float* Lim   = (const float*)d_in[2];   // (P,)
    const float* Bre   = (const float*)d_in[3];   // (P,H)
    const float* Bim   = (const float*)d_in[4];   // (P,H)
    const float* Cre   = (const float*)d_in[5];   // (H,P)
    const float* Cim   = (const float*)d_in[6];   // (H,P)
    const float* Dv    = (const float*)d_in[7];   // (H,)
    const float* lstep = (const float*)d_in[8];   // (P,1)
    float* out = (float*)d_out;

    cudaFuncSetAttribute(gemm_bu_mma,  cudaFuncAttributeMaxDynamicSharedMemorySize, 98304);
    cudaFuncSetAttribute(gemm_out_mma, cudaFuncAttributeMaxDynamicSharedMemorySize, 98304);

    prep_lambda_k<<<(PP + 255) / 256, 256>>>(Lre, Lim, lstep);
    prep_bbar_k<<<(PP * HH + 255) / 256, 256>>>(Bre, Bim);
    prep_cbf_k<<<(HH * PP + 255) / 256, 256>>>(Cre, Cim);
    prep_ubf_k<<<(LL * HH / 4 + 255) / 256, 256>>>(u);

    gemm_bu_mma<<<dim3(PP / 64, LL / 128), 256, 98304>>>();

    scanA_kernel<<<dim3(PP / 256, NC), 256>>>();
    scanB_kernel<<<PP, NC>>>();
    scanC_kernel<<<dim3(PP / 256, NC), 256>>>();

    gemm_out_mma<<<dim3(HH / 64, LL / 128), 256, 98304>>>(u, Dv, out);
}